// round 1
// baseline (speedup 1.0000x reference)
#include <cuda_runtime.h>
#include <math.h>

#define CN 512
#define HW 1024
#define BTN 32
#define NSP 32768               // 32*1024 = 2048*16
#define GROUPS 32
#define ATT_SCALE 0.044194173824159216f   // 512^-0.5
#define GN_EPS 1e-6f

// ------------------------------ scratch (device globals, no allocs) ---------
__device__ float g_hs[CN * NSP];            // normed activations (spatial, then temporal)
__device__ float g_q [CN * NSP];
__device__ float g_k [CN * NSP];
__device__ float g_v [CN * NSP];
__device__ float g_o [CN * NSP];            // attn output / temporal proj output
__device__ float g_s [CN * NSP];            // state after spatial residual
__device__ float g_attn[(size_t)BTN * HW * HW];  // spatial probs; reused as temporal attn out
__device__ float g_ps [BTN * GROUPS * HW];
__device__ float g_ps2[BTN * GROUPS * HW];
__device__ float g_mean[2048 * GROUPS];
__device__ float g_rstd[2048 * GROUPS];

// ------------------------------ spatial GroupNorm ---------------------------
// one block per (bt, group); reads x (B,C,T,H,W) coalesced over hw, writes
// hs[c][bt*1024+hw]
__global__ __launch_bounds__(256) void gn_spatial(
    const float* __restrict__ x, const float* __restrict__ gamma,
    const float* __restrict__ beta, float* __restrict__ hs)
{
    int bt = blockIdx.x >> 5, g = blockIdx.x & 31;
    int b = bt >> 4, t = bt & 15;
    int tid = threadIdx.x;
    float s = 0.f, s2 = 0.f;
#pragma unroll
    for (int ci = 0; ci < 16; ci++) {
        const float* p = x + ((size_t)((b * CN + g * 16 + ci) * 16 + t) << 10);
#pragma unroll
        for (int j = 0; j < 4; j++) {
            float v = p[tid + j * 256];
            s += v; s2 += v * v;
        }
    }
    __shared__ float red0[8], red1[8];
#pragma unroll
    for (int off = 16; off; off >>= 1) {
        s  += __shfl_xor_sync(0xffffffffu, s,  off);
        s2 += __shfl_xor_sync(0xffffffffu, s2, off);
    }
    if ((tid & 31) == 0) { red0[tid >> 5] = s; red1[tid >> 5] = s2; }
    __syncthreads();
    float S = 0.f, S2 = 0.f;
#pragma unroll
    for (int i = 0; i < 8; i++) { S += red0[i]; S2 += red1[i]; }
    float mean = S * (1.f / 16384.f);
    float var  = S2 * (1.f / 16384.f) - mean * mean;
    float rstd = rsqrtf(var + GN_EPS);
#pragma unroll
    for (int ci = 0; ci < 16; ci++) {
        int c = g * 16 + ci;
        const float* p = x + ((size_t)((b * CN + c) * 16 + t) << 10);
        float* q = hs + (size_t)c * NSP + (bt << 10);
        float gm = gamma[c], be = beta[c];
#pragma unroll
        for (int j = 0; j < 4; j++) {
            float v = p[tid + j * 256];
            q[tid + j * 256] = (v - mean) * rstd * gm + be;
        }
    }
}

// ------------------------------ projection GEMM -----------------------------
// Out[m][n] = sum_k W[m][k] * X[k][n] + bias[m] (+residual if mode==1)
// M=512, K=512, N=NSP, ldX=ldOut=NSP. 128x128x16 tiles, 8x8 per thread.
__global__ __launch_bounds__(256, 2) void gemm_proj(
    const float* __restrict__ W, const float* __restrict__ bias,
    const float* __restrict__ X, float* __restrict__ Out,
    const float* __restrict__ Res, int mode)
{
    __shared__ float As[16 * 136];
    __shared__ float Bs[16 * 128];
    int tid = threadIdx.x;
    int tx = tid & 15, ty = tid >> 4;
    int n0 = blockIdx.x << 7, m0 = blockIdx.y << 7;
    float acc[8][8] = {};
    int aRow = tid >> 2, aCol = (tid & 3) << 2;
    int bRow = tid >> 5, bCol = (tid & 31) << 2;
    for (int k0 = 0; k0 < 512; k0 += 16) {
#pragma unroll
        for (int r = 0; r < 2; r++) {
            int row = aRow + (r << 6);
            float4 a = *(const float4*)(W + (size_t)(m0 + row) * 512 + k0 + aCol);
            As[(aCol    ) * 136 + row] = a.x;
            As[(aCol + 1) * 136 + row] = a.y;
            As[(aCol + 2) * 136 + row] = a.z;
            As[(aCol + 3) * 136 + row] = a.w;
        }
#pragma unroll
        for (int r = 0; r < 2; r++) {
            int kr = bRow + (r << 3);
            *(float4*)(Bs + kr * 128 + bCol) =
                *(const float4*)(X + (size_t)(k0 + kr) * NSP + n0 + bCol);
        }
        __syncthreads();
#pragma unroll
        for (int kk = 0; kk < 16; kk++) {
            float4 a0 = *(const float4*)(As + kk * 136 + (ty << 2));
            float4 a1 = *(const float4*)(As + kk * 136 + 64 + (ty << 2));
            float4 b0 = *(const float4*)(Bs + kk * 128 + (tx << 2));
            float4 b1 = *(const float4*)(Bs + kk * 128 + 64 + (tx << 2));
            float ar[8] = {a0.x, a0.y, a0.z, a0.w, a1.x, a1.y, a1.z, a1.w};
            float br[8] = {b0.x, b0.y, b0.z, b0.w, b1.x, b1.y, b1.z, b1.w};
#pragma unroll
            for (int i = 0; i < 8; i++)
#pragma unroll
                for (int j = 0; j < 8; j++)
                    acc[i][j] = fmaf(ar[i], br[j], acc[i][j]);
        }
        __syncthreads();
    }
    int btb = n0 >> 10, bb = btb >> 4, tt = btb & 15;
    int hw0 = n0 & 1023;
#pragma unroll
    for (int i = 0; i < 8; i++) {
        int m = m0 + ((i < 4) ? (ty << 2) + i : 64 + (ty << 2) + i - 4);
        float bsv = bias[m];
        float4 o0 = make_float4(acc[i][0] + bsv, acc[i][1] + bsv, acc[i][2] + bsv, acc[i][3] + bsv);
        float4 o1 = make_float4(acc[i][4] + bsv, acc[i][5] + bsv, acc[i][6] + bsv, acc[i][7] + bsv);
        if (mode == 1) {
            const float* rp = Res + ((size_t)((bb * CN + m) * 16 + tt) << 10) + hw0;
            float4 r0 = *(const float4*)(rp + (tx << 2));
            float4 r1 = *(const float4*)(rp + 64 + (tx << 2));
            o0.x += r0.x; o0.y += r0.y; o0.z += r0.z; o0.w += r0.w;
            o1.x += r1.x; o1.y += r1.y; o1.z += r1.z; o1.w += r1.w;
        }
        *(float4*)(Out + (size_t)m * NSP + n0 + (tx << 2)) = o0;
        *(float4*)(Out + (size_t)m * NSP + n0 + 64 + (tx << 2)) = o1;
    }
}

// ------------------------------ spatial logits GEMM -------------------------
// P[bt][qp][kp] = scale * sum_c Q[c][bt*1024+qp] * K[c][bt*1024+kp]
__global__ __launch_bounds__(256, 2) void gemm_logits(
    const float* __restrict__ Q, const float* __restrict__ Km, float* __restrict__ P)
{
    __shared__ float As[16 * 128];
    __shared__ float Bs[16 * 128];
    int tid = threadIdx.x;
    int tx = tid & 15, ty = tid >> 4;
    int n0 = blockIdx.x << 7, m0 = blockIdx.y << 7;
    int bt = blockIdx.z;
    int base = bt << 10;
    float acc[8][8] = {};
    int lRow = tid >> 5, lCol = (tid & 31) << 2;
    for (int k0 = 0; k0 < 512; k0 += 16) {
#pragma unroll
        for (int r = 0; r < 2; r++) {
            int kr = lRow + (r << 3);
            *(float4*)(As + kr * 128 + lCol) =
                *(const float4*)(Q + (size_t)(k0 + kr) * NSP + base + m0 + lCol);
            *(float4*)(Bs + kr * 128 + lCol) =
                *(const float4*)(Km + (size_t)(k0 + kr) * NSP + base + n0 + lCol);
        }
        __syncthreads();
#pragma unroll
        for (int kk = 0; kk < 16; kk++) {
            float4 a0 = *(const float4*)(As + kk * 128 + (ty << 2));
            float4 a1 = *(const float4*)(As + kk * 128 + 64 + (ty << 2));
            float4 b0 = *(const float4*)(Bs + kk * 128 + (tx << 2));
            float4 b1 = *(const float4*)(Bs + kk * 128 + 64 + (tx << 2));
            float ar[8] = {a0.x, a0.y, a0.z, a0.w, a1.x, a1.y, a1.z, a1.w};
            float br[8] = {b0.x, b0.y, b0.z, b0.w, b1.x, b1.y, b1.z, b1.w};
#pragma unroll
            for (int i = 0; i < 8; i++)
#pragma unroll
                for (int j = 0; j < 8; j++)
                    acc[i][j] = fmaf(ar[i], br[j], acc[i][j]);
        }
        __syncthreads();
    }
    float* Pb = P + ((size_t)bt << 20);
#pragma unroll
    for (int i = 0; i < 8; i++) {
        int m = m0 + ((i < 4) ? (ty << 2) + i : 64 + (ty << 2) + i - 4);
        float4 o0 = make_float4(acc[i][0] * ATT_SCALE, acc[i][1] * ATT_SCALE,
                                acc[i][2] * ATT_SCALE, acc[i][3] * ATT_SCALE);
        float4 o1 = make_float4(acc[i][4] * ATT_SCALE, acc[i][5] * ATT_SCALE,
                                acc[i][6] * ATT_SCALE, acc[i][7] * ATT_SCALE);
        *(float4*)(Pb + (size_t)m * 1024 + n0 + (tx << 2)) = o0;
        *(float4*)(Pb + (size_t)m * 1024 + n0 + 64 + (tx << 2)) = o1;
    }
}

// ------------------------------ spatial softmax -----------------------------
__global__ __launch_bounds__(256) void softmax_k(float* __restrict__ P)
{
    int tid = threadIdx.x;
    float4* r = (float4*)(P + ((size_t)blockIdx.x << 10));
    float4 a = r[tid];
    float m = fmaxf(fmaxf(a.x, a.y), fmaxf(a.z, a.w));
    __shared__ float red[8];
#pragma unroll
    for (int off = 16; off; off >>= 1) m = fmaxf(m, __shfl_xor_sync(0xffffffffu, m, off));
    if ((tid & 31) == 0) red[tid >> 5] = m;
    __syncthreads();
    float M = red[0];
#pragma unroll
    for (int i = 1; i < 8; i++) M = fmaxf(M, red[i]);
    a.x = __expf(a.x - M); a.y = __expf(a.y - M);
    a.z = __expf(a.z - M); a.w = __expf(a.w - M);
    float s = a.x + a.y + a.z + a.w;
    __syncthreads();
#pragma unroll
    for (int off = 16; off; off >>= 1) s += __shfl_xor_sync(0xffffffffu, s, off);
    if ((tid & 31) == 0) red[tid >> 5] = s;
    __syncthreads();
    float S = red[0];
#pragma unroll
    for (int i = 1; i < 8; i++) S += red[i];
    float inv = 1.f / S;
    a.x *= inv; a.y *= inv; a.z *= inv; a.w *= inv;
    r[tid] = a;
}

// ------------------------------ attn @ V GEMM -------------------------------
// O[c][bt*1024+qp] = sum_k V[c][bt*1024+k] * P[bt][qp][k]
__global__ __launch_bounds__(256, 2) void gemm_av(
    const float* __restrict__ V, const float* __restrict__ P, float* __restrict__ Out)
{
    __shared__ float As[16 * 136];
    __shared__ float Bs[16 * 136];
    int tid = threadIdx.x;
    int tx = tid & 15, ty = tid >> 4;
    int n0 = blockIdx.x << 7;   // qp
    int m0 = blockIdx.y << 7;   // c
    int bt = blockIdx.z;
    float acc[8][8] = {};
    int aRow = tid >> 2, aCol = (tid & 3) << 2;
    const float* Pb = P + ((size_t)bt << 20);
    for (int k0 = 0; k0 < 1024; k0 += 16) {
#pragma unroll
        for (int r = 0; r < 2; r++) {
            int row = aRow + (r << 6);
            float4 a = *(const float4*)(V + (size_t)(m0 + row) * NSP + (bt << 10) + k0 + aCol);
            As[(aCol    ) * 136 + row] = a.x;
            As[(aCol + 1) * 136 + row] = a.y;
            As[(aCol + 2) * 136 + row] = a.z;
            As[(aCol + 3) * 136 + row] = a.w;
            float4 p = *(const float4*)(Pb + (size_t)(n0 + row) * 1024 + k0 + aCol);
            Bs[(aCol    ) * 136 + row] = p.x;
            Bs[(aCol + 1) * 136 + row] = p.y;
            Bs[(aCol + 2) * 136 + row] = p.z;
            Bs[(aCol + 3) * 136 + row] = p.w;
        }
        __syncthreads();
#pragma unroll
        for (int kk = 0; kk < 16; kk++) {
            float4 a0 = *(const float4*)(As + kk * 136 + (ty << 2));
            float4 a1 = *(const float4*)(As + kk * 136 + 64 + (ty << 2));
            float4 b0 = *(const float4*)(Bs + kk * 136 + (tx << 2));
            float4 b1 = *(const float4*)(Bs + kk * 136 + 64 + (tx << 2));
            float ar[8] = {a0.x, a0.y, a0.z, a0.w, a1.x, a1.y, a1.z, a1.w};
            float br[8] = {b0.x, b0.y, b0.z, b0.w, b1.x, b1.y, b1.z, b1.w};
#pragma unroll
            for (int i = 0; i < 8; i++)
#pragma unroll
                for (int j = 0; j < 8; j++)
                    acc[i][j] = fmaf(ar[i], br[j], acc[i][j]);
        }
        __syncthreads();
    }
#pragma unroll
    for (int i = 0; i < 8; i++) {
        int m = m0 + ((i < 4) ? (ty << 2) + i : 64 + (ty << 2) + i - 4);
        float4 o0 = make_float4(acc[i][0], acc[i][1], acc[i][2], acc[i][3]);
        float4 o1 = make_float4(acc[i][4], acc[i][5], acc[i][6], acc[i][7]);
        *(float4*)(Out + (size_t)m * NSP + (bt << 10) + n0 + (tx << 2)) = o0;
        *(float4*)(Out + (size_t)m * NSP + (bt << 10) + n0 + 64 + (tx << 2)) = o1;
    }
}

// ------------------------------ temporal stats ------------------------------
// pass 1: per (bt, g, hw) sums over 16 channels
__global__ __launch_bounds__(256) void tstats1(const float* __restrict__ S)
{
    int bt = blockIdx.x >> 5, g = blockIdx.x & 31;
    int tid = threadIdx.x;
#pragma unroll
    for (int j = 0; j < 4; j++) {
        int hw = tid + j * 256;
        float s = 0.f, s2 = 0.f;
#pragma unroll
        for (int ci = 0; ci < 16; ci++) {
            float v = S[(size_t)(g * 16 + ci) * NSP + (bt << 10) + hw];
            s += v; s2 += v * v;
        }
        g_ps [((size_t)blockIdx.x << 10) + hw] = s;
        g_ps2[((size_t)blockIdx.x << 10) + hw] = s2;
    }
}

// pass 2: reduce over t -> mean/rstd per (n=(b,hw), g)
__global__ __launch_bounds__(256) void tstats2()
{
    int hwc = blockIdx.x & 3, g = (blockIdx.x >> 2) & 31, b = blockIdx.x >> 7;
    int hw = (hwc << 8) + threadIdx.x;
    float s = 0.f, s2 = 0.f;
#pragma unroll
    for (int t = 0; t < 16; t++) {
        int idx = (((b * 16 + t) * 32 + g) << 10) + hw;
        s += g_ps[idx]; s2 += g_ps2[idx];
    }
    float mean = s * (1.f / 256.f);
    float var  = s2 * (1.f / 256.f) - mean * mean;
    int n = (b << 10) + hw;
    g_mean[n * 32 + g] = mean;
    g_rstd[n * 32 + g] = rsqrtf(var + GN_EPS);
}

// normalize + transpose into ht[c][(b,hw)*16+t]
__global__ __launch_bounds__(256) void tnorm(
    const float* __restrict__ S, const float* __restrict__ gamma,
    const float* __restrict__ beta, float* __restrict__ ht)
{
    __shared__ float sm[4 * 2176];
    __shared__ float smean[128], srstd[128];
    int hw0 = blockIdx.x << 7, c0 = blockIdx.y << 2, b = blockIdx.z;
    int g = c0 >> 4;
    int tid = threadIdx.x;
    if (tid < 128) {
        int n = (b << 10) + hw0 + tid;
        smean[tid] = g_mean[n * 32 + g];
        srstd[tid] = g_rstd[n * 32 + g];
    }
    __syncthreads();
    for (int idx = tid; idx < 8192; idx += 256) {
        int c = idx >> 11, rem = idx & 2047, t = rem >> 7, col = rem & 127;
        float v = S[(size_t)(c0 + c) * NSP + ((size_t)((b << 4) + t) << 10) + hw0 + col];
        float h = (v - smean[col]) * srstd[col] * gamma[c0 + c] + beta[c0 + c];
        sm[c * 2176 + col * 17 + t] = h;
    }
    __syncthreads();
    for (int idx = tid; idx < 8192; idx += 256) {
        int c = idx >> 11, jj = idx & 2047;
        ht[(size_t)(c0 + c) * NSP + ((size_t)((b << 10) + hw0) << 4) + jj] =
            sm[c * 2176 + ((jj >> 4) * 17) + (jj & 15)];
    }
}

// ------------------------------ temporal attention (fused) ------------------
__global__ __launch_bounds__(256) void temporal_attn(
    const float* __restrict__ Q, const float* __restrict__ K,
    const float* __restrict__ V, float* __restrict__ O)
{
    __shared__ float sq[16][16], sk[16][16], sv[16][16], sp[16][17];
    int n = blockIdx.x;
    int col0 = n << 4;
    int tid = threadIdx.x, hi = tid >> 4, lo = tid & 15;
    float acc = 0.f;
    for (int c0 = 0; c0 < 512; c0 += 16) {
        sq[hi][lo] = Q[(size_t)(c0 + hi) * NSP + col0 + lo];
        sk[hi][lo] = K[(size_t)(c0 + hi) * NSP + col0 + lo];
        __syncthreads();
#pragma unroll
        for (int cc = 0; cc < 16; cc++)
            acc = fmaf(sq[cc][hi], sk[cc][lo], acc);
        __syncthreads();
    }
    sp[hi][lo] = acc * ATT_SCALE;
    __syncthreads();
    if (tid < 16) {
        float m = -1e30f;
#pragma unroll
        for (int j = 0; j < 16; j++) m = fmaxf(m, sp[tid][j]);
        float s = 0.f;
#pragma unroll
        for (int j = 0; j < 16; j++) {
            float e = __expf(sp[tid][j] - m);
            sp[tid][j] = e; s += e;
        }
        float inv = 1.f / s;
#pragma unroll
        for (int j = 0; j < 16; j++) sp[tid][j] *= inv;
    }
    __syncthreads();
    for (int c0 = 0; c0 < 512; c0 += 16) {
        sv[hi][lo] = V[(size_t)(c0 + hi) * NSP + col0 + lo];
        __syncthreads();
        float o = 0.f;
#pragma unroll
        for (int t2 = 0; t2 < 16; t2++)
            o = fmaf(sv[hi][t2], sp[lo][t2], o);
        O[(size_t)(c0 + hi) * NSP + col0 + lo] = o;
        __syncthreads();
    }
}

// ------------------------------ final: residual + transpose to output -------
__global__ __launch_bounds__(256) void final_out(
    const float* __restrict__ S, const float* __restrict__ A2, float* __restrict__ Out)
{
    __shared__ float sm[128 * 17];
    int hw0 = blockIdx.x << 7, c = blockIdx.y, b = blockIdx.z;
    int tid = threadIdx.x;
    for (int idx = tid; idx < 2048; idx += 256)
        sm[(idx >> 4) * 17 + (idx & 15)] =
            A2[(size_t)c * NSP + ((size_t)((b << 10) + hw0) << 4) + idx];
    __syncthreads();
    for (int idx = tid; idx < 2048; idx += 256) {
        int t = idx >> 7, col = idx & 127;
        Out[((size_t)((b * CN + c) * 16 + t) << 10) + hw0 + col] =
            S[(size_t)c * NSP + ((size_t)((b << 4) + t) << 10) + hw0 + col] + sm[col * 17 + t];
    }
}

// ------------------------------ launch --------------------------------------
extern "C" void kernel_launch(void* const* d_in, const int* in_sizes, int n_in,
                              void* d_out, int out_size)
{
    const float* x       = (const float*)d_in[0];
    const float* gamma_s = (const float*)d_in[1];
    const float* beta_s  = (const float*)d_in[2];
    const float* wq_s    = (const float*)d_in[3];
    const float* bq_s    = (const float*)d_in[4];
    const float* wk_s    = (const float*)d_in[5];
    const float* bk_s    = (const float*)d_in[6];
    const float* wv_s    = (const float*)d_in[7];
    const float* bv_s    = (const float*)d_in[8];
    const float* wo_s    = (const float*)d_in[9];
    const float* bo_s    = (const float*)d_in[10];
    const float* gamma_t = (const float*)d_in[11];
    const float* beta_t  = (const float*)d_in[12];
    const float* wq_t    = (const float*)d_in[13];
    const float* bq_t    = (const float*)d_in[14];
    const float* wk_t    = (const float*)d_in[15];
    const float* bk_t    = (const float*)d_in[16];
    const float* wv_t    = (const float*)d_in[17];
    const float* bv_t    = (const float*)d_in[18];
    const float* wo_t    = (const float*)d_in[19];
    const float* bo_t    = (const float*)d_in[20];

    float *hs, *q, *k, *v, *o, *s, *attn;
    cudaGetSymbolAddress((void**)&hs,   g_hs);
    cudaGetSymbolAddress((void**)&q,    g_q);
    cudaGetSymbolAddress((void**)&k,    g_k);
    cudaGetSymbolAddress((void**)&v,    g_v);
    cudaGetSymbolAddress((void**)&o,    g_o);
    cudaGetSymbolAddress((void**)&s,    g_s);
    cudaGetSymbolAddress((void**)&attn, g_attn);

    dim3 gp(256, 4);

    // ---- spatial attention ----
    gn_spatial<<<1024, 256>>>(x, gamma_s, beta_s, hs);
    gemm_proj<<<gp, 256>>>(wq_s, bq_s, hs, q, (const float*)0, 0);
    gemm_proj<<<gp, 256>>>(wk_s, bk_s, hs, k, (const float*)0, 0);
    gemm_proj<<<gp, 256>>>(wv_s, bv_s, hs, v, (const float*)0, 0);
    gemm_logits<<<dim3(8, 8, 32), 256>>>(q, k, attn);
    softmax_k<<<32768, 256>>>(attn);
    gemm_av<<<dim3(8, 4, 32), 256>>>(v, attn, o);
    gemm_proj<<<gp, 256>>>(wo_s, bo_s, o, s, x, 1);   // + residual -> state S

    // ---- temporal attention ----
    tstats1<<<1024, 256>>>(s);
    tstats2<<<256, 256>>>();
    tnorm<<<dim3(8, 128, 2), 256>>>(s, gamma_t, beta_t, hs);
    gemm_proj<<<gp, 256>>>(wq_t, bq_t, hs, q, (const float*)0, 0);
    gemm_proj<<<gp, 256>>>(wk_t, bk_t, hs, k, (const float*)0, 0);
    gemm_proj<<<gp, 256>>>(wv_t, bv_t, hs, v, (const float*)0, 0);
    temporal_attn<<<2048, 256>>>(q, k, v, attn);      // attn reused as O_t
    gemm_proj<<<gp, 256>>>(wo_t, bo_t, attn, o, (const float*)0, 0);
    final_out<<<dim3(8, 512, 2), 256>>>(s, o, (float*)d_out);
}